// round 5
// baseline (speedup 1.0000x reference)
#include <cuda_runtime.h>
#include <math.h>

#define NRES 768
#define MSAD 384
#define NH 12
#define PAIRD 128
#define OUTD 384
#define PROJ 1152
#define FINALD 2112

typedef unsigned long long ull;

// ---------------- f32x2 helpers (Blackwell packed fp32) ---------------------
__device__ __forceinline__ ull pk2(float v) {
    ull r; asm("mov.b64 %0, {%1, %1};" : "=l"(r) : "f"(v)); return r;
}
__device__ __forceinline__ ull pk2two(float lo, float hi) {
    ull r; asm("mov.b64 %0, {%1, %2};" : "=l"(r) : "f"(lo), "f"(hi)); return r;
}
__device__ __forceinline__ void fma2(ull& d, ull a, ull b) {
    asm("fma.rn.f32x2 %0, %1, %2, %0;" : "+l"(d) : "l"(a), "l"(b));
}
__device__ __forceinline__ float2 upk(ull v) {
    float2 r; asm("mov.b64 {%0, %1}, %2;" : "=f"(r.x), "=f"(r.y) : "l"(v)); return r;
}

// ---------------- scratch (device globals; no allocation allowed) ----------
__device__ float g_wcat[MSAD * PROJ];
__device__ float g_bcat[PROJ];
__device__ float g_pw[NH];
__device__ float g_proj[NRES * PROJ];
__device__ float g_qpack[NH * NRES * 28];  // [h][i][0..15]=q*sw, [16..27]=pw*qp
__device__ float g_kpack[NH * NRES * 32];  // [h][j][0..15]=k, [16..27]=kp, [28]=-0.5*pw*|kp|^2
__device__ float g_vpack2[NH * NRES * 40]; // [h][j][0..15]=v, [16..39]=vp (p*3+c)
__device__ float g_logits[NH * NRES * NRES]; // attn (post-softmax) for k4b
__device__ float g_final[NRES * FINALD];
__device__ float g_part[3][NRES * OUTD];   // split-K partials for k5

// ---------------- K0: concat projection weights, softplus(tpw) -------------
__global__ void k0_prep(const float* __restrict__ qw, const float* __restrict__ qb,
                        const float* __restrict__ kvw, const float* __restrict__ kvb,
                        const float* __restrict__ qpw, const float* __restrict__ qpb,
                        const float* __restrict__ kvpw, const float* __restrict__ kvpb,
                        const float* __restrict__ tpw) {
    int idx = blockIdx.x * blockDim.x + threadIdx.x;
    if (idx < MSAD * PROJ) {
        int k = idx / PROJ, o = idx % PROJ;
        float v;
        if (o < 192)      v = qw[k * 192 + o];
        else if (o < 576) v = kvw[k * 384 + (o - 192)];
        else if (o < 720) v = qpw[k * 144 + (o - 576)];
        else              v = kvpw[k * 432 + (o - 720)];
        g_wcat[idx] = v;
    }
    if (idx < PROJ) {
        float b;
        if (idx < 192)      b = qb[idx];
        else if (idx < 576) b = kvb[idx - 192];
        else if (idx < 720) b = qpb[idx - 576];
        else                b = kvpb[idx - 720];
        g_bcat[idx] = b;
    }
    if (idx < NH) {
        float x = tpw[idx];
        float sp = (x > 20.f) ? x : log1pf(__expf(x));
        g_pw[idx] = sp * 0.13608276348795434f; // sqrt(1/54)
    }
}

// ---------------- K1a: projection GEMM 768x1152x384 (f32x2) -----------------
__global__ __launch_bounds__(256) void k1a_gemm(const float* __restrict__ in1d) {
    __shared__ float sA[32][65];
    __shared__ ull sB2[32][32];
    int tid = threadIdx.x;
    int tx = tid & 15, ty = tid >> 4;
    int m0 = blockIdx.y * 64, n0 = blockIdx.x * 64;
    ull acc[4][2] = {};
    for (int k0 = 0; k0 < MSAD; k0 += 32) {
        for (int idx = tid; idx < 64 * 32; idx += 256) {
            int m = idx >> 5, kk = idx & 31;
            sA[kk][m] = in1d[(m0 + m) * MSAD + k0 + kk];
        }
        for (int idx = tid; idx < 32 * 32; idx += 256) {
            int kk = idx >> 5, op = idx & 31;
            float2 w = *(const float2*)(g_wcat + (size_t)(k0 + kk) * PROJ + n0 + op * 2);
            sB2[kk][op] = pk2two(w.x, w.y);
        }
        __syncthreads();
#pragma unroll
        for (int kk = 0; kk < 32; kk++) {
            ulonglong2 b01 = *(const ulonglong2*)&sB2[kk][tx * 2];
#pragma unroll
            for (int r = 0; r < 4; r++) {
                ull a2 = pk2(sA[kk][ty * 4 + r]);
                fma2(acc[r][0], a2, b01.x);
                fma2(acc[r][1], a2, b01.y);
            }
        }
        __syncthreads();
    }
#pragma unroll
    for (int r = 0; r < 4; r++) {
        int m = m0 + ty * 4 + r, o = n0 + tx * 4;
        float2 lo = upk(acc[r][0]), hi = upk(acc[r][1]);
        g_proj[(size_t)m * PROJ + o + 0] = lo.x + g_bcat[o + 0];
        g_proj[(size_t)m * PROJ + o + 1] = lo.y + g_bcat[o + 1];
        g_proj[(size_t)m * PROJ + o + 2] = hi.x + g_bcat[o + 2];
        g_proj[(size_t)m * PROJ + o + 3] = hi.y + g_bcat[o + 3];
    }
}

// ---------------- K1b: apply rotations, pack q/k/v --------------------------
__global__ __launch_bounds__(256) void k1b_pack(const float* __restrict__ rot,
                                                const float* __restrict__ trans) {
    __shared__ float sp[PROJ];
    __shared__ float srot[9], strans[3], spw[12];
    __shared__ float sg[192 * 3];
    int n = blockIdx.x, tid = threadIdx.x;
    for (int t = tid; t < PROJ; t += 256) sp[t] = g_proj[n * PROJ + t];
    if (tid < 9) srot[tid] = rot[n * 9 + tid];
    if (tid < 3) strans[tid] = trans[n * 3 + tid];
    if (tid < 12) spw[tid] = g_pw[tid];
    __syncthreads();

    if (tid < 192) {
        int h = tid >> 4, d = tid & 15;
        g_qpack[(h * NRES + n) * 28 + d] = sp[tid] * 0.14433756729740643f; // 1/sqrt(48)
    }
    for (int t = tid; t < 384; t += 256) {
        int h = t >> 5, d = t & 31;
        if (d < 16) g_kpack[(h * NRES + n) * 32 + d] = sp[192 + t];
        else        g_vpack2[((size_t)h * NRES + n) * 40 + (d - 16)] = sp[192 + t];
    }
    if (tid < 192) {
        float l0, l1, l2;
        if (tid < 48) { l0 = sp[576 + tid]; l1 = sp[576 + 48 + tid]; l2 = sp[576 + 96 + tid]; }
        else { int vs = tid - 48; l0 = sp[720 + vs]; l1 = sp[720 + 144 + vs]; l2 = sp[720 + 288 + vs]; }
#pragma unroll
        for (int c = 0; c < 3; c++)
            sg[tid * 3 + c] = srot[c * 3 + 0] * l0 + srot[c * 3 + 1] * l1 + srot[c * 3 + 2] * l2 + strans[c];
    }
    __syncthreads();
    if (tid < 48) {
        int h = tid >> 2, p = tid & 3;
        float pw = spw[h];
#pragma unroll
        for (int c = 0; c < 3; c++)
            g_qpack[(h * NRES + n) * 28 + 16 + p * 3 + c] = pw * sg[tid * 3 + c];
    } else if (tid < 192) {
        int vs = tid - 48, h = vs / 12, s = vs % 12;
        if (s < 4) {
#pragma unroll
            for (int c = 0; c < 3; c++)
                g_kpack[(h * NRES + n) * 32 + 16 + s * 3 + c] = sg[tid * 3 + c];
        } else {
#pragma unroll
            for (int c = 0; c < 3; c++)
                g_vpack2[((size_t)h * NRES + n) * 40 + 16 + (s - 4) * 3 + c] = sg[tid * 3 + c];
        }
    }
    if (tid >= 192 && tid < 204) {
        int h = tid - 192;
        float s2 = 0.f;
        for (int s = 0; s < 4; s++)
            for (int c = 0; c < 3; c++) {
                float v = sg[(48 + h * 12 + s) * 3 + c];
                s2 += v * v;
            }
        g_kpack[(h * NRES + n) * 32 + 28] = -0.5f * spw[h] * s2;
    }
}

// ---------------- kA: fused a2d + qk-logits + softmax + a_over_2d -----------
// One block per query row i. Dynamic smem layout:
//   [0)       sA    float[256*33]   33792 B  (in2d staging / pass2 reduce buf)
//   [33792)   sattn float[12*768]   36864 B
//   [70656)   sw2   ull[128*6]       6144 B
//   [76800)   sq2   ull[12*14]       1344 B
//   [78144)   sb    float[12]          48 B
#define KA_SMEM 78208

__global__ __launch_bounds__(256) void kA_fused(const float* __restrict__ in2d,
                                                const float* __restrict__ w2d,
                                                const float* __restrict__ b2d) {
    extern __shared__ char smraw[];
    float* sA    = (float*)smraw;
    float* sattn = (float*)(smraw + 33792);
    ull*   sw2   = (ull*)(smraw + 70656);
    ull*   sq2   = (ull*)(smraw + 76800);
    float* sb    = (float*)(smraw + 78144);

    int i = blockIdx.x, tid = threadIdx.x;

    // stage w2d (pairs over heads) and q row
    for (int f = tid; f < 128 * 6; f += 256) {
        int c = f / 6, hp = f % 6;
        float2 w = *(const float2*)(w2d + c * 12 + hp * 2);
        sw2[f] = pk2two(w.x, w.y);
    }
    for (int f = tid; f < 12 * 14; f += 256) {
        int h = f / 14, dp = f % 14;
        const float* qp = g_qpack + ((size_t)h * NRES + i) * 28 + dp * 2;
        sq2[f] = pk2two(qp[0], qp[1]);
    }
    if (tid < 12) sb[tid] = b2d[tid];
    __syncthreads();

    // ---- pass1: a2d + qk logits (thread = one j within a 256-chunk) --------
    for (int c = 0; c < 3; c++) {
        ull acc[6] = {};
        const float* src = in2d + ((size_t)i * NRES + c * 256) * PAIRD;
        for (int k0 = 0; k0 < 128; k0 += 32) {
            __syncthreads();
            for (int f = tid; f < 2048; f += 256) {
                int r = f >> 3, c4 = f & 7;
                float4 v = __ldg((const float4*)(src + (size_t)r * PAIRD + k0) + c4);
                float* d = &sA[r * 33 + c4 * 4];
                d[0] = v.x; d[1] = v.y; d[2] = v.z; d[3] = v.w;
            }
            __syncthreads();
#pragma unroll
            for (int k = 0; k < 32; k++) {
                ull a2 = pk2(sA[tid * 33 + k]);
                const ull* w = &sw2[(k0 + k) * 6];
                fma2(acc[0], a2, w[0]); fma2(acc[1], a2, w[1]);
                fma2(acc[2], a2, w[2]); fma2(acc[3], a2, w[3]);
                fma2(acc[4], a2, w[4]); fma2(acc[5], a2, w[5]);
            }
        }
        float res[12];
#pragma unroll
        for (int hp = 0; hp < 6; hp++) {
            float2 v = upk(acc[hp]);
            res[2 * hp] = v.x; res[2 * hp + 1] = v.y;
        }
        int jg = c * 256 + tid;
#pragma unroll
        for (int h = 0; h < 12; h++) {
            const ull* kp2 = (const ull*)(g_kpack + ((size_t)h * NRES + jg) * 32);
            ull wacc = 0;
#pragma unroll
            for (int dp = 0; dp < 14; dp++)
                fma2(wacc, sq2[h * 14 + dp], __ldg(&kp2[dp]));
            float2 t = upk(wacc);
            float logit = t.x + t.y + __ldg((const float*)kp2 + 28)
                        + (res[h] + sb[h]) * 0.5773502691896258f;
            sattn[h * NRES + jg] = logit;
        }
    }
    __syncthreads();

    // ---- softmax: warp per head -------------------------------------------
    int w = tid >> 5, lane = tid & 31;
    for (int hh = w; hh < 12; hh += 8) {
        float vals[24];
        float m = -1e30f;
#pragma unroll
        for (int t = 0; t < 24; t++) {
            vals[t] = sattn[hh * NRES + t * 32 + lane];
            m = fmaxf(m, vals[t]);
        }
#pragma unroll
        for (int o = 16; o > 0; o >>= 1) m = fmaxf(m, __shfl_xor_sync(~0u, m, o));
        float s = 0.f;
#pragma unroll
        for (int t = 0; t < 24; t++) {
            float e = __expf(vals[t] - m);
            vals[t] = e; s += e;
        }
#pragma unroll
        for (int o = 16; o > 0; o >>= 1) s += __shfl_xor_sync(~0u, s, o);
        float inv = 1.f / s;
#pragma unroll
        for (int t = 0; t < 24; t++) sattn[hh * NRES + t * 32 + lane] = vals[t] * inv;
    }
    __syncthreads();

    // write attn row out for k4b (coalesced float4)
    for (int f = tid; f < 2304; f += 256) {
        int h = f / 192, q = f % 192;
        ((float4*)(g_logits + ((size_t)h * NRES + i) * NRES))[q] =
            ((const float4*)(sattn + h * NRES))[q];
    }

    // ---- pass2: a_over_2d (in2d re-read — L2 hot) --------------------------
    // warp w: jh = w>>2 (j half), hg = w&3 (3 heads hg*3..+2); lane = col quad
    int jh = w >> 2, hg = w & 3;
    const ulonglong2* b2 = (const ulonglong2*)(in2d + ((size_t)i * NRES + jh * 384) * PAIRD) + lane;
    ull acc[3][2] = {};
    for (int j = 0; j < 384; j += 4) {
        ulonglong2 d0 = __ldg(b2 + (size_t)(j + 0) * 32);
        ulonglong2 d1 = __ldg(b2 + (size_t)(j + 1) * 32);
        ulonglong2 d2 = __ldg(b2 + (size_t)(j + 2) * 32);
        ulonglong2 d3 = __ldg(b2 + (size_t)(j + 3) * 32);
#pragma unroll
        for (int k = 0; k < 3; k++) {
            float4 a = *(const float4*)&sattn[(hg * 3 + k) * NRES + jh * 384 + j];
            fma2(acc[k][0], pk2(a.x), d0.x); fma2(acc[k][1], pk2(a.x), d0.y);
            fma2(acc[k][0], pk2(a.y), d1.x); fma2(acc[k][1], pk2(a.y), d1.y);
            fma2(acc[k][0], pk2(a.z), d2.x); fma2(acc[k][1], pk2(a.z), d2.y);
            fma2(acc[k][0], pk2(a.w), d3.x); fma2(acc[k][1], pk2(a.w), d3.y);
        }
    }
    // combine halves via smem (reuse sA region)
    ull* sred = (ull*)smraw;
    __syncthreads();
    if (jh == 1) {
        ull* dst = &sred[(size_t)(hg * 32 + lane) * 6];
#pragma unroll
        for (int k = 0; k < 3; k++) { dst[k * 2] = acc[k][0]; dst[k * 2 + 1] = acc[k][1]; }
    }
    __syncthreads();
    if (jh == 0) {
        const ull* ot = &sred[(size_t)(hg * 32 + lane) * 6];
#pragma unroll
        for (int k = 0; k < 3; k++) {
            float2 lo = upk(acc[k][0]), lo2 = upk(ot[k * 2]);
            float2 hi = upk(acc[k][1]), hi2 = upk(ot[k * 2 + 1]);
            float4 outv = make_float4(lo.x + lo2.x, lo.y + lo2.y, hi.x + hi2.x, hi.y + hi2.y);
            *(float4*)(g_final + (size_t)i * FINALD + 576 + (hg * 3 + k) * PAIRD + 4 * lane) = outv;
        }
    }
}

// ---------------- K4b: per-head GEMM for v / vp + rotate-back epilogue ------
__global__ __launch_bounds__(320) void k4b_vattend(const float* __restrict__ rot,
                                                   const float* __restrict__ trans) {
    __shared__ float2 sattn2[64][65];
    __shared__ ull svp[64 * 20];
    __shared__ float srpg[64][24];
    int i0 = blockIdx.x * 64, h = blockIdx.y;
    int tid = threadIdx.x, il = tid & 63, dg = tid >> 6;
    ull acc[4] = {};
    for (int j0 = 0; j0 < NRES; j0 += 64) {
        for (int f = tid; f < 4096; f += 320) {
            int r = f >> 6, c = f & 63;
            float a = g_logits[((size_t)h * NRES + i0 + r) * NRES + j0 + c];
            sattn2[r][c] = make_float2(a, a);
        }
        for (int f = tid; f < 1280; f += 320)
            svp[f] = __ldg((const ull*)(g_vpack2 + ((size_t)h * NRES + j0) * 40) + f);
        __syncthreads();
#pragma unroll 4
        for (int jj = 0; jj < 64; jj++) {
            ull a2 = *(const ull*)&sattn2[il][jj];
            const ulonglong2* wv = (const ulonglong2*)&svp[jj * 20 + dg * 4];
            ulonglong2 w01 = wv[0], w23 = wv[1];
            fma2(acc[0], a2, w01.x); fma2(acc[1], a2, w01.y);
            fma2(acc[2], a2, w23.x); fma2(acc[3], a2, w23.y);
        }
        __syncthreads();
    }
    int n_i = i0 + il;
    float v[8];
#pragma unroll
    for (int q = 0; q < 4; q++) {
        float2 t = upk(acc[q]);
        v[2 * q] = t.x; v[2 * q + 1] = t.y;
    }
    if (dg < 2) {
        float* dst = g_final + (size_t)n_i * FINALD + h * 16 + dg * 8;
#pragma unroll
        for (int t = 0; t < 8; t++) dst[t] = v[t];
    } else {
        int d0 = (dg - 2) * 8;
#pragma unroll
        for (int t = 0; t < 8; t++) srpg[il][d0 + t] = v[t];
    }
    __syncthreads();
    for (int f = tid; f < 512; f += 320) {
        int ii = f >> 3, p = f & 7;
        int n = i0 + ii;
        float vx = srpg[ii][p * 3 + 0] - trans[n * 3 + 0];
        float vy = srpg[ii][p * 3 + 1] - trans[n * 3 + 1];
        float vz = srpg[ii][p * 3 + 2] - trans[n * 3 + 2];
        float nn = 1e-8f;
#pragma unroll
        for (int ic = 0; ic < 3; ic++) {
            float rl = rot[n * 9 + 0 + ic] * vx + rot[n * 9 + 3 + ic] * vy + rot[n * 9 + 6 + ic] * vz;
            g_final[(size_t)n * FINALD + 192 + ic * 96 + h * 8 + p] = rl;
            nn += rl * rl;
        }
        g_final[(size_t)n * FINALD + 480 + h * 8 + p] = sqrtf(nn);
    }
}

// ---------------- K5: output GEMM 768x384, K=2112, split-K=3 (f32x2) --------
__global__ __launch_bounds__(256) void k5_out(const float* __restrict__ out_w) {
    __shared__ float sA[32][65];
    __shared__ ull sB2[32][32];
    int tid = threadIdx.x, tx = tid & 15, ty = tid >> 4;
    int m0 = blockIdx.y * 64, n0 = blockIdx.x * 64;
    int kb = blockIdx.z * 704;
    ull acc[4][2] = {};
    for (int k0 = kb; k0 < kb + 704; k0 += 32) {
        for (int idx = tid; idx < 64 * 32; idx += 256) {
            int m = idx >> 5, kk = idx & 31;
            sA[kk][m] = g_final[(size_t)(m0 + m) * FINALD + k0 + kk];
        }
        for (int idx = tid; idx < 32 * 32; idx += 256) {
            int kk = idx >> 5, op = idx & 31;
            float2 wv = *(const float2*)(out_w + (size_t)(k0 + kk) * OUTD + n0 + op * 2);
            sB2[kk][op] = pk2two(wv.x, wv.y);
        }
        __syncthreads();
#pragma unroll
        for (int kk = 0; kk < 32; kk++) {
            ulonglong2 b01 = *(const ulonglong2*)&sB2[kk][tx * 2];
#pragma unroll
            for (int r = 0; r < 4; r++) {
                ull a2 = pk2(sA[kk][ty * 4 + r]);
                fma2(acc[r][0], a2, b01.x);
                fma2(acc[r][1], a2, b01.y);
            }
        }
        __syncthreads();
    }
#pragma unroll
    for (int r = 0; r < 4; r++) {
        int m = m0 + ty * 4 + r, o = n0 + tx * 4;
        float2 lo = upk(acc[r][0]), hi = upk(acc[r][1]);
        *(float4*)(g_part[blockIdx.z] + (size_t)m * OUTD + o) =
            make_float4(lo.x, lo.y, hi.x, hi.y);
    }
}

__global__ void k5r_reduce(const float* __restrict__ out_b, float* __restrict__ out) {
    int idx = blockIdx.x * 256 + threadIdx.x;
    if (idx < NRES * OUTD) {
        out[idx] = g_part[0][idx] + g_part[1][idx] + g_part[2][idx] + out_b[idx % OUTD];
    }
}

// ---------------- launch ----------------------------------------------------
extern "C" void kernel_launch(void* const* d_in, const int* in_sizes, int n_in,
                              void* d_out, int out_size) {
    const float* in1d  = (const float*)d_in[0];
    const float* in2d  = (const float*)d_in[1];
    const float* rot   = (const float*)d_in[2];
    const float* trans = (const float*)d_in[3];
    const float* qw    = (const float*)d_in[4];
    const float* qb    = (const float*)d_in[5];
    const float* kvw   = (const float*)d_in[6];
    const float* kvb   = (const float*)d_in[7];
    const float* qpw   = (const float*)d_in[8];
    const float* qpb   = (const float*)d_in[9];
    const float* kvpw  = (const float*)d_in[10];
    const float* kvpb  = (const float*)d_in[11];
    const float* tpw   = (const float*)d_in[12];
    const float* w2d   = (const float*)d_in[13];
    const float* b2d   = (const float*)d_in[14];
    const float* ow    = (const float*)d_in[15];
    const float* ob    = (const float*)d_in[16];
    float* out = (float*)d_out;

    cudaFuncSetAttribute(kA_fused, cudaFuncAttributeMaxDynamicSharedMemorySize, KA_SMEM);

    k0_prep<<<1728, 256>>>(qw, qb, kvw, kvb, qpw, qpb, kvpw, kvpb, tpw);
    k1a_gemm<<<dim3(18, 12), 256>>>(in1d);
    k1b_pack<<<768, 256>>>(rot, trans);
    kA_fused<<<768, 256, KA_SMEM>>>(in2d, w2d, b2d);
    k4b_vattend<<<dim3(12, 12), 320>>>(rot, trans);
    k5_out<<<dim3(6, 12, 3), 256>>>(ow);
    k5r_reduce<<<1152, 256>>>(ob, out);
}

// round 6
// speedup vs baseline: 1.8209x; 1.8209x over previous
#include <cuda_runtime.h>
#include <math.h>

#define NRES 768
#define MSAD 384
#define NH 12
#define PAIRD 128
#define OUTD 384
#define PROJ 1152
#define FINALD 2112

typedef unsigned long long ull;

// ---------------- f32x2 helpers (Blackwell packed fp32) ---------------------
__device__ __forceinline__ ull pk2(float v) {
    ull r; asm("mov.b64 %0, {%1, %1};" : "=l"(r) : "f"(v)); return r;
}
__device__ __forceinline__ ull pk2two(float lo, float hi) {
    ull r; asm("mov.b64 %0, {%1, %2};" : "=l"(r) : "f"(lo), "f"(hi)); return r;
}
__device__ __forceinline__ void fma2(ull& d, ull a, ull b) {
    asm("fma.rn.f32x2 %0, %1, %2, %0;" : "+l"(d) : "l"(a), "l"(b));
}
__device__ __forceinline__ float2 upk(ull v) {
    float2 r; asm("mov.b64 {%0, %1}, %2;" : "=f"(r.x), "=f"(r.y) : "l"(v)); return r;
}

// ---------------- scratch (device globals; no allocation allowed) ----------
__device__ float g_wcat[MSAD * PROJ];
__device__ float g_bcat[PROJ];
__device__ float g_pw[NH];
__device__ float g_proj[NRES * PROJ];
__device__ float g_qpack[NH * NRES * 28];
__device__ float g_kpack[NH * NRES * 32];
__device__ float g_vpack2[NH * NRES * 40];
__device__ float g_logits[NH * NRES * NRES];
__device__ float g_final[NRES * FINALD];
__device__ float g_part[3][NRES * OUTD];

// ---------------- K0 --------------------------------------------------------
__global__ void k0_prep(const float* __restrict__ qw, const float* __restrict__ qb,
                        const float* __restrict__ kvw, const float* __restrict__ kvb,
                        const float* __restrict__ qpw, const float* __restrict__ qpb,
                        const float* __restrict__ kvpw, const float* __restrict__ kvpb,
                        const float* __restrict__ tpw) {
    int idx = blockIdx.x * blockDim.x + threadIdx.x;
    if (idx < MSAD * PROJ) {
        int k = idx / PROJ, o = idx % PROJ;
        float v;
        if (o < 192)      v = qw[k * 192 + o];
        else if (o < 576) v = kvw[k * 384 + (o - 192)];
        else if (o < 720) v = qpw[k * 144 + (o - 576)];
        else              v = kvpw[k * 432 + (o - 720)];
        g_wcat[idx] = v;
    }
    if (idx < PROJ) {
        float b;
        if (idx < 192)      b = qb[idx];
        else if (idx < 576) b = kvb[idx - 192];
        else if (idx < 720) b = qpb[idx - 576];
        else                b = kvpb[idx - 720];
        g_bcat[idx] = b;
    }
    if (idx < NH) {
        float x = tpw[idx];
        float sp = (x > 20.f) ? x : log1pf(__expf(x));
        g_pw[idx] = sp * 0.13608276348795434f; // sqrt(1/54)
    }
}

// ---------------- K1a: projection GEMM 768x1152x384 (f32x2) -----------------
__global__ __launch_bounds__(256) void k1a_gemm(const float* __restrict__ in1d) {
    __shared__ float sA[32][65];
    __shared__ ull sB2[32][32];
    int tid = threadIdx.x;
    int tx = tid & 15, ty = tid >> 4;
    int m0 = blockIdx.y * 64, n0 = blockIdx.x * 64;
    ull acc[4][2] = {};
    for (int k0 = 0; k0 < MSAD; k0 += 32) {
        for (int idx = tid; idx < 64 * 32; idx += 256) {
            int m = idx >> 5, kk = idx & 31;
            sA[kk][m] = in1d[(m0 + m) * MSAD + k0 + kk];
        }
        for (int idx = tid; idx < 32 * 32; idx += 256) {
            int kk = idx >> 5, op = idx & 31;
            float2 w = *(const float2*)(g_wcat + (size_t)(k0 + kk) * PROJ + n0 + op * 2);
            sB2[kk][op] = pk2two(w.x, w.y);
        }
        __syncthreads();
#pragma unroll
        for (int kk = 0; kk < 32; kk++) {
            ulonglong2 b01 = *(const ulonglong2*)&sB2[kk][tx * 2];
#pragma unroll
            for (int r = 0; r < 4; r++) {
                ull a2 = pk2(sA[kk][ty * 4 + r]);
                fma2(acc[r][0], a2, b01.x);
                fma2(acc[r][1], a2, b01.y);
            }
        }
        __syncthreads();
    }
#pragma unroll
    for (int r = 0; r < 4; r++) {
        int m = m0 + ty * 4 + r, o = n0 + tx * 4;
        float2 lo = upk(acc[r][0]), hi = upk(acc[r][1]);
        g_proj[(size_t)m * PROJ + o + 0] = lo.x + g_bcat[o + 0];
        g_proj[(size_t)m * PROJ + o + 1] = lo.y + g_bcat[o + 1];
        g_proj[(size_t)m * PROJ + o + 2] = hi.x + g_bcat[o + 2];
        g_proj[(size_t)m * PROJ + o + 3] = hi.y + g_bcat[o + 3];
    }
}

// ---------------- K1b: apply rotations, pack q/k/v --------------------------
__global__ __launch_bounds__(256) void k1b_pack(const float* __restrict__ rot,
                                                const float* __restrict__ trans) {
    __shared__ float sp[PROJ];
    __shared__ float srot[9], strans[3], spw[12];
    __shared__ float sg[192 * 3];
    int n = blockIdx.x, tid = threadIdx.x;
    for (int t = tid; t < PROJ; t += 256) sp[t] = g_proj[n * PROJ + t];
    if (tid < 9) srot[tid] = rot[n * 9 + tid];
    if (tid < 3) strans[tid] = trans[n * 3 + tid];
    if (tid < 12) spw[tid] = g_pw[tid];
    __syncthreads();

    if (tid < 192) {
        int h = tid >> 4, d = tid & 15;
        g_qpack[(h * NRES + n) * 28 + d] = sp[tid] * 0.14433756729740643f; // 1/sqrt(48)
    }
    for (int t = tid; t < 384; t += 256) {
        int h = t >> 5, d = t & 31;
        if (d < 16) g_kpack[(h * NRES + n) * 32 + d] = sp[192 + t];
        else        g_vpack2[((size_t)h * NRES + n) * 40 + (d - 16)] = sp[192 + t];
    }
    if (tid < 192) {
        float l0, l1, l2;
        if (tid < 48) { l0 = sp[576 + tid]; l1 = sp[576 + 48 + tid]; l2 = sp[576 + 96 + tid]; }
        else { int vs = tid - 48; l0 = sp[720 + vs]; l1 = sp[720 + 144 + vs]; l2 = sp[720 + 288 + vs]; }
#pragma unroll
        for (int c = 0; c < 3; c++)
            sg[tid * 3 + c] = srot[c * 3 + 0] * l0 + srot[c * 3 + 1] * l1 + srot[c * 3 + 2] * l2 + strans[c];
    }
    __syncthreads();
    if (tid < 48) {
        int h = tid >> 2, p = tid & 3;
        float pw = spw[h];
#pragma unroll
        for (int c = 0; c < 3; c++)
            g_qpack[(h * NRES + n) * 28 + 16 + p * 3 + c] = pw * sg[tid * 3 + c];
    } else if (tid < 192) {
        int vs = tid - 48, h = vs / 12, s = vs % 12;
        if (s < 4) {
#pragma unroll
            for (int c = 0; c < 3; c++)
                g_kpack[(h * NRES + n) * 32 + 16 + s * 3 + c] = sg[tid * 3 + c];
        } else {
#pragma unroll
            for (int c = 0; c < 3; c++)
                g_vpack2[((size_t)h * NRES + n) * 40 + 16 + (s - 4) * 3 + c] = sg[tid * 3 + c];
        }
    }
    if (tid >= 192 && tid < 204) {
        int h = tid - 192;
        float s2 = 0.f;
        for (int s = 0; s < 4; s++)
            for (int c = 0; c < 3; c++) {
                float v = sg[(48 + h * 12 + s) * 3 + c];
                s2 += v * v;
            }
        g_kpack[(h * NRES + n) * 32 + 28] = -0.5f * spw[h] * s2;
    }
}

// ---------------- K2: a2d GEMM, double-buffered ------------------------------
// dyn smem: sA[2][256*33] @0 (67584), sw2 ull[768] @67584 (6144), sb @73728
#define K2_SMEM 73792
__global__ __launch_bounds__(256) void k2_a2d(const float* __restrict__ in2d,
                                              const float* __restrict__ w2d,
                                              const float* __restrict__ b2d) {
    extern __shared__ char smraw[];
    float* sA  = (float*)smraw;                 // [2][256*33]
    ull*   sw2 = (ull*)(smraw + 67584);
    float* sb  = (float*)(smraw + 73728);
    int tid = threadIdx.x;
    for (int f = tid; f < 128 * 6; f += 256) {
        int c = f / 6, hp = f % 6;
        float2 w = *(const float2*)(w2d + c * 12 + hp * 2);
        sw2[f] = pk2two(w.x, w.y);
    }
    if (tid < 12) sb[tid] = b2d[tid];
    size_t p0 = (size_t)blockIdx.x * 256;
    const float* src = in2d + p0 * PAIRD;
    // stage chunk 0
    for (int f = tid; f < 2048; f += 256) {
        int r = f >> 3, c4 = f & 7;
        float4 v = __ldg((const float4*)(src + (size_t)r * PAIRD) + c4);
        float* d = &sA[r * 33 + c4 * 4];
        d[0] = v.x; d[1] = v.y; d[2] = v.z; d[3] = v.w;
    }
    __syncthreads();
    ull acc[6] = {};
#pragma unroll
    for (int ck = 0; ck < 4; ck++) {
        if (ck < 3) {
            int k0n = (ck + 1) * 32;
            float* dstb = sA + ((ck + 1) & 1) * 8448;
            for (int f = tid; f < 2048; f += 256) {
                int r = f >> 3, c4 = f & 7;
                float4 v = __ldg((const float4*)(src + (size_t)r * PAIRD + k0n) + c4);
                float* d = &dstb[r * 33 + c4 * 4];
                d[0] = v.x; d[1] = v.y; d[2] = v.z; d[3] = v.w;
            }
        }
        const float* A = sA + (ck & 1) * 8448 + tid * 33;
        int kb = ck * 32;
#pragma unroll
        for (int k = 0; k < 32; k++) {
            ull a2 = pk2(A[k]);
            const ull* w = &sw2[(kb + k) * 6];
            fma2(acc[0], a2, w[0]); fma2(acc[1], a2, w[1]);
            fma2(acc[2], a2, w[2]); fma2(acc[3], a2, w[3]);
            fma2(acc[4], a2, w[4]); fma2(acc[5], a2, w[5]);
        }
        __syncthreads();
    }
    size_t p = p0 + tid;
    int i = (int)(p / NRES), j = (int)(p % NRES);
    float res[12];
#pragma unroll
    for (int hp = 0; hp < 6; hp++) {
        float2 v = upk(acc[hp]);
        res[2 * hp] = v.x; res[2 * hp + 1] = v.y;
    }
#pragma unroll
    for (int h = 0; h < 12; h++)
        g_logits[((size_t)h * NRES + i) * NRES + j] = (res[h] + sb[h]) * 0.5773502691896258f;
}

// ---------------- K3: qk scalar+point logits + softmax ----------------------
__global__ __launch_bounds__(256) void k3_softmax() {
    __shared__ float srow[8][NRES];
    __shared__ float su[8][28];
    __shared__ float sredA[8], sredB[8];
    int h = blockIdx.y, i0 = blockIdx.x * 8;
    int tid = threadIdx.x;
    for (int t = tid; t < 8 * 28; t += 256) {
        int i8 = t / 28, d = t % 28;
        su[i8][d] = g_qpack[(size_t)(h * NRES + (i0 + i8)) * 28 + d];
    }
    __syncthreads();
    for (int jj = 0; jj < 3; jj++) {
        int j = jj * 256 + tid;
        float wr[32];
        const float4* kp4 = (const float4*)(g_kpack + (size_t)(h * NRES + j) * 32);
#pragma unroll
        for (int q = 0; q < 8; q++) {
            float4 v = kp4[q];
            wr[q * 4 + 0] = v.x; wr[q * 4 + 1] = v.y; wr[q * 4 + 2] = v.z; wr[q * 4 + 3] = v.w;
        }
#pragma unroll
        for (int i8 = 0; i8 < 8; i8++) {
            float acc = wr[28];
#pragma unroll
            for (int d = 0; d < 28; d++) acc += su[i8][d] * wr[d];
            srow[i8][j] = acc + g_logits[(size_t)(h * NRES + (i0 + i8)) * NRES + j];
        }
    }
    __syncthreads();
    int lane = tid & 31, wid = tid >> 5;
    for (int i8 = 0; i8 < 8; i8++) {
        float m = -1e30f;
#pragma unroll
        for (int jj = 0; jj < 3; jj++) m = fmaxf(m, srow[i8][jj * 256 + tid]);
#pragma unroll
        for (int o = 16; o > 0; o >>= 1) m = fmaxf(m, __shfl_xor_sync(~0u, m, o));
        if (lane == 0) sredA[wid] = m;
        __syncthreads();
        m = sredA[0];
#pragma unroll
        for (int w = 1; w < 8; w++) m = fmaxf(m, sredA[w]);
        float s = 0.f;
#pragma unroll
        for (int jj = 0; jj < 3; jj++) {
            float e = __expf(srow[i8][jj * 256 + tid] - m);
            srow[i8][jj * 256 + tid] = e;
            s += e;
        }
#pragma unroll
        for (int o = 16; o > 0; o >>= 1) s += __shfl_xor_sync(~0u, s, o);
        if (lane == 0) sredB[wid] = s;
        __syncthreads();
        s = sredB[0];
#pragma unroll
        for (int w = 1; w < 8; w++) s += sredB[w];
        float inv = 1.f / s;
#pragma unroll
        for (int jj = 0; jj < 3; jj++) {
            int j = jj * 256 + tid;
            g_logits[(size_t)(h * NRES + (i0 + i8)) * NRES + j] = srow[i8][j] * inv;
        }
        __syncthreads();
    }
}

// ---------------- K4a: a_over_2d, smem-staged + double-buffered -------------
// One block per query row i, 256 threads. thread = (g = head triple, cp = col pair)
// dyn smem: sattn float[12*768] @0 (36864), sbuf float[2][16*128] @36864 (16384)
#define K4A_SMEM 53248
__global__ __launch_bounds__(256) void k4a_aover(const float* __restrict__ in2d) {
    extern __shared__ char smraw[];
    float* sattn = (float*)smraw;
    float* sbuf  = (float*)(smraw + 36864);
    int i = blockIdx.x, tid = threadIdx.x;

    for (int f = tid; f < 2304; f += 256) {
        int h = f / 192, q = f % 192;
        ((float4*)(sattn + h * NRES))[q] =
            __ldg((const float4*)(g_logits + ((size_t)h * NRES + i) * NRES) + q);
    }
    const float* src = in2d + (size_t)i * NRES * PAIRD;
    // stage tile 0 (rows 0..15)
#pragma unroll
    for (int t = 0; t < 2; t++) {
        int f = tid + t * 256;
        int r = f >> 5, c4 = f & 31;
        ((float4*)sbuf)[r * 32 + c4] = __ldg((const float4*)(src + (size_t)r * PAIRD) + c4);
    }
    __syncthreads();

    int g = tid >> 6, cp = tid & 63;
    ull acc0 = 0, acc1 = 0, acc2 = 0;
    const float* a0p = sattn + (g * 3 + 0) * NRES;
    const float* a1p = sattn + (g * 3 + 1) * NRES;
    const float* a2p = sattn + (g * 3 + 2) * NRES;

    for (int s = 0; s < 48; s++) {
        if (s + 1 < 48) {
            const float* nsrc = src + (size_t)(s + 1) * 16 * PAIRD;
            float* dstb = sbuf + ((s + 1) & 1) * 2048;
#pragma unroll
            for (int t = 0; t < 2; t++) {
                int f = tid + t * 256;
                int r = f >> 5, c4 = f & 31;
                ((float4*)dstb)[r * 32 + c4] = __ldg((const float4*)(nsrc + (size_t)r * PAIRD) + c4);
            }
        }
        const ull* bb = (const ull*)(sbuf + (s & 1) * 2048) + cp;
        int j0 = s * 16;
#pragma unroll
        for (int q4 = 0; q4 < 4; q4++) {
            float4 A0 = *(const float4*)(a0p + j0 + q4 * 4);
            float4 A1 = *(const float4*)(a1p + j0 + q4 * 4);
            float4 A2 = *(const float4*)(a2p + j0 + q4 * 4);
            const ull* dp = bb + (size_t)q4 * 256;
            ull d0 = dp[0], d1 = dp[64], d2 = dp[128], d3 = dp[192];
            fma2(acc0, pk2(A0.x), d0); fma2(acc1, pk2(A1.x), d0); fma2(acc2, pk2(A2.x), d0);
            fma2(acc0, pk2(A0.y), d1); fma2(acc1, pk2(A1.y), d1); fma2(acc2, pk2(A2.y), d1);
            fma2(acc0, pk2(A0.z), d2); fma2(acc1, pk2(A1.z), d2); fma2(acc2, pk2(A2.z), d2);
            fma2(acc0, pk2(A0.w), d3); fma2(acc1, pk2(A1.w), d3); fma2(acc2, pk2(A2.w), d3);
        }
        __syncthreads();
    }
    float2 r0 = upk(acc0), r1 = upk(acc1), r2 = upk(acc2);
    float* dst = g_final + (size_t)i * FINALD + 576;
    *(float2*)(dst + (g * 3 + 0) * PAIRD + 2 * cp) = r0;
    *(float2*)(dst + (g * 3 + 1) * PAIRD + 2 * cp) = r1;
    *(float2*)(dst + (g * 3 + 2) * PAIRD + 2 * cp) = r2;
}

// ---------------- K4b: per-head GEMM for v / vp + rotate-back epilogue ------
__global__ __launch_bounds__(320) void k4b_vattend(const float* __restrict__ rot,
                                                   const float* __restrict__ trans) {
    __shared__ float2 sattn2[64][65];
    __shared__ ull svp[64 * 20];
    __shared__ float srpg[64][24];
    int i0 = blockIdx.x * 64, h = blockIdx.y;
    int tid = threadIdx.x, il = tid & 63, dg = tid >> 6;
    ull acc[4] = {};
    for (int j0 = 0; j0 < NRES; j0 += 64) {
        for (int f = tid; f < 4096; f += 320) {
            int r = f >> 6, c = f & 63;
            float a = g_logits[((size_t)h * NRES + i0 + r) * NRES + j0 + c];
            sattn2[r][c] = make_float2(a, a);
        }
        for (int f = tid; f < 1280; f += 320)
            svp[f] = __ldg((const ull*)(g_vpack2 + ((size_t)h * NRES + j0) * 40) + f);
        __syncthreads();
#pragma unroll 4
        for (int jj = 0; jj < 64; jj++) {
            ull a2 = *(const ull*)&sattn2[il][jj];
            const ulonglong2* wv = (const ulonglong2*)&svp[jj * 20 + dg * 4];
            ulonglong2 w01 = wv[0], w23 = wv[1];
            fma2(acc[0], a2, w01.x); fma2(acc[1], a2, w01.y);
            fma2(acc[2], a2, w23.x); fma2(acc[3], a2, w23.y);
        }
        __syncthreads();
    }
    int n_i = i0 + il;
    float v[8];
#pragma unroll
    for (int q = 0; q < 4; q++) {
        float2 t = upk(acc[q]);
        v[2 * q] = t.x; v[2 * q + 1] = t.y;
    }
    if (dg < 2) {
        float* dst = g_final + (size_t)n_i * FINALD + h * 16 + dg * 8;
#pragma unroll
        for (int t = 0; t < 8; t++) dst[t] = v[t];
    } else {
        int d0 = (dg - 2) * 8;
#pragma unroll
        for (int t = 0; t < 8; t++) srpg[il][d0 + t] = v[t];
    }
    __syncthreads();
    for (int f = tid; f < 512; f += 320) {
        int ii = f >> 3, p = f & 7;
        int n = i0 + ii;
        float vx = srpg[ii][p * 3 + 0] - trans[n * 3 + 0];
        float vy = srpg[ii][p * 3 + 1] - trans[n * 3 + 1];
        float vz = srpg[ii][p * 3 + 2] - trans[n * 3 + 2];
        float nn = 1e-8f;
#pragma unroll
        for (int ic = 0; ic < 3; ic++) {
            float rl = rot[n * 9 + 0 + ic] * vx + rot[n * 9 + 3 + ic] * vy + rot[n * 9 + 6 + ic] * vz;
            g_final[(size_t)n * FINALD + 192 + ic * 96 + h * 8 + p] = rl;
            nn += rl * rl;
        }
        g_final[(size_t)n * FINALD + 480 + h * 8 + p] = sqrtf(nn);
    }
}

// ---------------- K5: output GEMM 768x384, K=2112, split-K=3 (f32x2) --------
__global__ __launch_bounds__(256) void k5_out(const float* __restrict__ out_w) {
    __shared__ float sA[32][65];
    __shared__ ull sB2[32][32];
    int tid = threadIdx.x, tx = tid & 15, ty = tid >> 4;
    int m0 = blockIdx.y * 64, n0 = blockIdx.x * 64;
    int kb = blockIdx.z * 704;
    ull acc[4][2] = {};
    for (int k0 = kb; k0 < kb + 704; k0 += 32) {
        for (int idx = tid; idx < 64 * 32; idx += 256) {
            int m = idx >> 5, kk = idx & 31;
            sA[kk][m] = g_final[(size_t)(m0 + m) * FINALD + k0 + kk];
        }
        for (int idx = tid; idx < 32 * 32; idx += 256) {
            int kk = idx >> 5, op = idx & 31;
            float2 wv = *(const float2*)(out_w + (size_t)(k0 + kk) * OUTD + n0 + op * 2);
            sB2[kk][op] = pk2two(wv.x, wv.y);
        }
        __syncthreads();
#pragma unroll
        for (int kk = 0; kk < 32; kk++) {
            ulonglong2 b01 = *(const ulonglong2*)&sB2[kk][tx * 2];
#pragma unroll
            for (int r = 0; r < 4; r++) {
                ull a2 = pk2(sA[kk][ty * 4 + r]);
                fma2(acc[r][0], a2, b01.x);
                fma2(acc[r][1], a2, b01.y);
            }
        }
        __syncthreads();
    }
#pragma unroll
    for (int r = 0; r < 4; r++) {
        int m = m0 + ty * 4 + r, o = n0 + tx * 4;
        float2 lo = upk(acc[r][0]), hi = upk(acc[r][1]);
        *(float4*)(g_part[blockIdx.z] + (size_t)m * OUTD + o) =
            make_float4(lo.x, lo.y, hi.x, hi.y);
    }
}

__global__ void k5r_reduce(const float* __restrict__ out_b, float* __restrict__ out) {
    int idx = blockIdx.x * 256 + threadIdx.x;
    if (idx < NRES * OUTD) {
        out[idx] = g_part[0][idx] + g_part[1][idx] + g_part[2][idx] + out_b[idx % OUTD];
    }
}

// ---------------- launch ----------------------------------------------------
extern "C" void kernel_launch(void* const* d_in, const int* in_sizes, int n_in,
                              void* d_out, int out_size) {
    const float* in1d  = (const float*)d_in[0];
    const float* in2d  = (const float*)d_in[1];
    const float* rot   = (const float*)d_in[2];
    const float* trans = (const float*)d_in[3];
    const float* qw    = (const float*)d_in[4];
    const float* qb    = (const float*)d_in[5];
    const float* kvw   = (const float*)d_in[6];
    const float* kvb   = (const float*)d_in[7];
    const float* qpw   = (const float*)d_in[8];
    const float* qpb   = (const float*)d_in[9];
    const float* kvpw  = (const float*)d_in[10];
    const float* kvpb  = (const float*)d_in[11];
    const float* tpw   = (const float*)d_in[12];
    const float* w2d   = (const float*)d_in[13];
    const float* b2d   = (const float*)d_in[14];
    const float* ow    = (const float*)d_in[15];
    const float* ob    = (const float*)d_in[16];
    float* out = (float*)d_out;

    cudaFuncSetAttribute(k2_a2d, cudaFuncAttributeMaxDynamicSharedMemorySize, K2_SMEM);
    cudaFuncSetAttribute(k4a_aover, cudaFuncAttributeMaxDynamicSharedMemorySize, K4A_SMEM);

    k0_prep<<<1728, 256>>>(qw, qb, kvw, kvb, qpw, qpb, kvpw, kvpb, tpw);
    k1a_gemm<<<dim3(18, 12), 256>>>(in1d);
    k1b_pack<<<768, 256>>>(rot, trans);
    k2_a2d<<<2304, 256, K2_SMEM>>>(in2d, w2d, b2d);
    k3_softmax<<<dim3(96, 12), 256>>>();
    k4a_aover<<<768, 256, K4A_SMEM>>>(in2d);
    k4b_vattend<<<dim3(12, 12), 320>>>(rot, trans);
    k5_out<<<dim3(6, 12, 3), 256>>>(ow);
    k5r_reduce<<<1152, 256>>>(ob, out);
}